// round 14
// baseline (speedup 1.0000x reference)
#include <cuda_runtime.h>
#include <cuda_bf16.h>
#include <cstdint>

// ParallelLinear: out[b,t,o] = sum_i x[b,t,i] * W[t,o,i] + bias[t,o]
// B=512, T=1024, ISIZE=OSIZE=64, fp32.
// R13: R7 mainloop verbatim (bf16-split mma.sync, k/n-permuted fragments,
//   register x prefetch, STG.128 epilogue), but BLOCK=256/ROWS=256 so the
//   W prologue is amortized over 2x rows, plus streaming cache hints
//   (__ldcs on x, __stcs on out) for zero-reuse data.

#define TT    1024
#define BB    512
#define KK    64
#define OO    64
#define BLOCK 256
#define ROWS  256

typedef unsigned int u32;

// ---- smem byte offsets ----
#define SM_BIAS 0                          // 64 floats = 256 B
#define SM_BHI  256                        // 64 rows * 128 B = 8192
#define SM_BLO  (SM_BHI + OO * 128)
#define SM_TOTAL (SM_BLO + OO * 128)       // 16640

__device__ __forceinline__ u32 smem_u32(const void* p) {
    u32 a;
    asm("{ .reg .u64 t; cvta.to.shared.u64 t, %1; cvt.u32.u64 %0, t; }" : "=r"(a) : "l"(p));
    return a;
}

// split fp32 pair -> packed bf16x2 hi and lo
__device__ __forceinline__ void split2(float ax, float ay, u32 &hi, u32 &lo) {
    float2 v = { ax, ay };
    __nv_bfloat162 hp = __float22bfloat162_rn(v);
    u32 h = *(u32*)&hp;
    float hx = __uint_as_float(h << 16);
    float hy = __uint_as_float(h & 0xFFFF0000u);
    float2 r = { v.x - hx, v.y - hy };
    __nv_bfloat162 lp = __float22bfloat162_rn(r);
    hi = h;
    lo = *(u32*)&lp;
}

// W staging-write offset with XOR swizzle (row = staged n-position, ip = staged pair idx)
__device__ __forceinline__ u32 stage_off(int row, int ip) {
    return (u32)(row * 128 + ((((ip >> 2) ^ (row & 7)) & 7) << 4) + ((ip & 3) << 2));
}

__device__ __forceinline__ void ldmx4(u32 &r0, u32 &r1, u32 &r2, u32 &r3, u32 addr) {
    asm volatile("ldmatrix.sync.aligned.m8n8.x4.shared.b16 {%0,%1,%2,%3}, [%4];"
                 : "=r"(r0), "=r"(r1), "=r"(r2), "=r"(r3) : "r"(addr));
}

__device__ __forceinline__ void mma_bf16(float* d, const u32* a, u32 b0, u32 b1) {
    asm volatile(
        "mma.sync.aligned.m16n8k16.row.col.f32.bf16.bf16.f32 "
        "{%0,%1,%2,%3}, {%4,%5,%6,%7}, {%8,%9}, {%0,%1,%2,%3};"
        : "+f"(d[0]), "+f"(d[1]), "+f"(d[2]), "+f"(d[3])
        : "r"(a[0]), "r"(a[1]), "r"(a[2]), "r"(a[3]), "r"(b0), "r"(b1));
}

__global__ __launch_bounds__(BLOCK, 2)
void ParallelLinear_59133109732019_kernel(
    const float* __restrict__ x,     // [B, T, 64]
    const float* __restrict__ W,     // [T, 64, 64]  (W[t][o][i])
    const float* __restrict__ bias,  // [T, 64]
    float* __restrict__ out)         // [B, T, 64]
{
    extern __shared__ char smem[];
    const u32 sb = smem_u32(smem);

    const int t       = blockIdx.y;
    const int rowBase = blockIdx.x * ROWS;
    const int tid     = threadIdx.x;
    const int wid     = tid >> 5;        // 0..7
    const int lane    = tid & 31;
    const int g       = lane >> 2;       // row within 8-group
    const int q       = lane & 3;        // fragment column selector

    // x fragment base: rows (rowBase + wid*32 + mt*16 + g [+8]), col 4q (k-permuted)
    const size_t xrstride = (size_t)TT * KK;
    const float* xbase[2];
    #pragma unroll
    for (int mt = 0; mt < 2; mt++)
        xbase[mt] = x + (size_t)(rowBase + wid * 32 + mt * 16 + g) * xrstride
                      + (size_t)t * KK + 4 * q;

    // ---- prefetch ks=0 x data (streaming loads; one float4 = one A-frag half) ----
    float4 xf[2][2];
    #pragma unroll
    for (int mt = 0; mt < 2; mt++) {
        xf[mt][0] = __ldcs((const float4*)(xbase[mt]));                  // row g
        xf[mt][1] = __ldcs((const float4*)(xbase[mt] + 8 * xrstride));   // row g+8
    }

    // ---- stage W[t] hi/lo with k-perm (sigma) and n-perm (pi) baked in ----
    //      (256 threads: only 8 iterations each — half of R7's prologue work)
    {
        const float2* Wg = (const float2*)(W + (size_t)t * (OO * KK));
        #pragma unroll
        for (int k = 0; k < (OO * KK / 2) / BLOCK; k++) {  // 8 iters
            int p = k * BLOCK + tid;
            int o = p >> 5, ip = p & 31;                   // o row, source i-pair
            u32 hi, lo;
            float2 v = Wg[p];
            split2(v.x, v.y, hi, lo);
            // k-perm: pair cp within 16-block -> cp' = (cp&1)*4 + (cp>>1)
            int blk = ip >> 3, cp = ip & 7;
            int ipp = (blk << 3) | (((cp & 1) << 2) | (cp >> 1));
            // n-perm: o = 16m + 4q + 2b + j -> row' = 16m + 8b + 2q + j
            int m = o >> 4, qq = (o >> 2) & 3, bb = (o >> 1) & 1, j = o & 1;
            int rowp = (m << 4) | (bb << 3) | (qq << 1) | j;
            u32 off = stage_off(rowp, ipp);
            *(u32*)(smem + SM_BHI + off) = hi;
            *(u32*)(smem + SM_BLO + off) = lo;
        }
        if (tid < OO) ((float*)(smem + SM_BIAS))[tid] = bias[(size_t)t * OO + tid];
    }
    __syncthreads();

    // ---- accumulators: 2 m-tiles x 8 n-tiles x 4 fp32 ----
    float d[2][8][4];
    #pragma unroll
    for (int mt = 0; mt < 2; mt++)
        #pragma unroll
        for (int nt = 0; nt < 8; nt++)
            #pragma unroll
            for (int e = 0; e < 4; e++) d[mt][nt][e] = 0.0f;

    // B-fragment ldmatrix lane->address components
    const int b_row  = (lane & 7) + ((lane >> 4) << 3);
    const int b_cadd = (lane >> 3) & 1;

    #pragma unroll
    for (int ks = 0; ks < 4; ks++) {
        // prefetch next k-step's x (streaming)
        float4 xn[2][2];
        if (ks < 3) {
            #pragma unroll
            for (int mt = 0; mt < 2; mt++) {
                const float* bp = xbase[mt] + (ks + 1) * 16;
                xn[mt][0] = __ldcs((const float4*)(bp));
                xn[mt][1] = __ldcs((const float4*)(bp + 8 * xrstride));
            }
        }

        // build bf16 hi/lo A fragments (k-permuted: float4 -> R0/R2, R1/R3)
        u32 ah[2][4], al[2][4];
        #pragma unroll
        for (int mt = 0; mt < 2; mt++) {
            split2(xf[mt][0].x, xf[mt][0].y, ah[mt][0], al[mt][0]);   // row g,   k-low
            split2(xf[mt][1].x, xf[mt][1].y, ah[mt][1], al[mt][1]);   // row g+8, k-low
            split2(xf[mt][0].z, xf[mt][0].w, ah[mt][2], al[mt][2]);   // row g,   k-high
            split2(xf[mt][1].z, xf[mt][1].w, ah[mt][3], al[mt][3]);   // row g+8, k-high
        }

        const int c0 = ks * 2;
        #pragma unroll
        for (int np = 0; np < 4; np++) {
            int n  = np * 16 + b_row;
            int ch = c0 + b_cadd;
            u32 off = (u32)(n * 128 + (((ch ^ (n & 7)) & 7) << 4));
            u32 bh0, bh1, bh2, bh3, bl0, bl1, bl2, bl3;
            ldmx4(bh0, bh1, bh2, bh3, sb + SM_BHI + off);
            ldmx4(bl0, bl1, bl2, bl3, sb + SM_BLO + off);

            #pragma unroll
            for (int mt = 0; mt < 2; mt++) {
                mma_bf16(d[mt][2 * np],     ah[mt], bh0, bh1);   // hi*hi
                mma_bf16(d[mt][2 * np + 1], ah[mt], bh2, bh3);
                mma_bf16(d[mt][2 * np],     ah[mt], bl0, bl1);   // hi*lo
                mma_bf16(d[mt][2 * np + 1], ah[mt], bl2, bl3);
                mma_bf16(d[mt][2 * np],     al[mt], bh0, bh1);   // lo*hi
                mma_bf16(d[mt][2 * np + 1], al[mt], bh2, bh3);
            }
        }

        #pragma unroll
        for (int mt = 0; mt < 2; mt++) {
            xf[mt][0] = xn[mt][0];
            xf[mt][1] = xn[mt][1];
        }
    }

    // ---- epilogue: n-perm makes nt-pairs contiguous -> streaming STG.128 ----
    const float* sBias = (const float*)(smem + SM_BIAS);
    #pragma unroll
    for (int mt = 0; mt < 2; mt++) {
        int r0 = rowBase + wid * 32 + mt * 16 + g;
        float* o0 = out + (size_t)r0 * (TT * OO) + (size_t)t * OO;
        float* o1 = o0 + (size_t)8 * (TT * OO);
        #pragma unroll
        for (int m = 0; m < 4; m++) {
            int c = 16 * m + 4 * q;        // true cols c..c+3
            float4 bv = *(const float4*)(sBias + c);
            float4 v0 = { d[mt][2 * m][0] + bv.x, d[mt][2 * m][1] + bv.y,
                          d[mt][2 * m + 1][0] + bv.z, d[mt][2 * m + 1][1] + bv.w };
            float4 v1 = { d[mt][2 * m][2] + bv.x, d[mt][2 * m][3] + bv.y,
                          d[mt][2 * m + 1][2] + bv.z, d[mt][2 * m + 1][3] + bv.w };
            __stcs((float4*)(o0 + c), v0); // row r0
            __stcs((float4*)(o1 + c), v1); // row r0 + 8
        }
    }
}

extern "C" void kernel_launch(void* const* d_in, const int* in_sizes, int n_in,
                              void* d_out, int out_size)
{
    const float* x    = (const float*)d_in[0];   // 512*1024*64 fp32
    const float* W    = (const float*)d_in[1];   // 1024*64*64 fp32
    const float* bias = (const float*)d_in[2];   // 1024*64 fp32
    float* out        = (float*)d_out;           // 512*1024*64 fp32

    cudaFuncSetAttribute(ParallelLinear_59133109732019_kernel,
                         cudaFuncAttributeMaxDynamicSharedMemorySize, SM_TOTAL);

    dim3 grid(BB / ROWS, TT);   // (2, 1024)
    ParallelLinear_59133109732019_kernel<<<grid, BLOCK, SM_TOTAL>>>(x, W, bias, out);
}

// round 15
// speedup vs baseline: 1.0314x; 1.0314x over previous
#include <cuda_runtime.h>
#include <cuda_bf16.h>
#include <cstdint>

// ParallelLinear: out[b,t,o] = sum_i x[b,t,i] * W[t,o,i] + bias[t,o]
// B=512, T=1024, ISIZE=OSIZE=64, fp32.
// R14: R7 verbatim EXCEPT the x double-buffer is removed (ks=0 prefetched
//   before the W prologue; ks>=1 loaded just-in-time) to cut ~30 live regs,
//   enabling __launch_bounds__(128, 5): 5 CTAs/SM = 20 warps for latency
//   hiding and CTA phase pipelining.

#define TT    1024
#define BB    512
#define KK    64
#define OO    64
#define BLOCK 128
#define ROWS  128

typedef unsigned int u32;

// ---- smem byte offsets ----
#define SM_BIAS 0                          // 64 floats = 256 B
#define SM_BHI  256                        // 64 rows * 128 B = 8192
#define SM_BLO  (SM_BHI + OO * 128)
#define SM_TOTAL (SM_BLO + OO * 128)       // 16640

__device__ __forceinline__ u32 smem_u32(const void* p) {
    u32 a;
    asm("{ .reg .u64 t; cvta.to.shared.u64 t, %1; cvt.u32.u64 %0, t; }" : "=r"(a) : "l"(p));
    return a;
}

// split fp32 pair -> packed bf16x2 hi and lo
__device__ __forceinline__ void split2(float ax, float ay, u32 &hi, u32 &lo) {
    float2 v = { ax, ay };
    __nv_bfloat162 hp = __float22bfloat162_rn(v);
    u32 h = *(u32*)&hp;
    float hx = __uint_as_float(h << 16);
    float hy = __uint_as_float(h & 0xFFFF0000u);
    float2 r = { v.x - hx, v.y - hy };
    __nv_bfloat162 lp = __float22bfloat162_rn(r);
    hi = h;
    lo = *(u32*)&lp;
}

// W staging-write offset with XOR swizzle (row = staged n-position, ip = staged pair idx)
__device__ __forceinline__ u32 stage_off(int row, int ip) {
    return (u32)(row * 128 + ((((ip >> 2) ^ (row & 7)) & 7) << 4) + ((ip & 3) << 2));
}

__device__ __forceinline__ void ldmx4(u32 &r0, u32 &r1, u32 &r2, u32 &r3, u32 addr) {
    asm volatile("ldmatrix.sync.aligned.m8n8.x4.shared.b16 {%0,%1,%2,%3}, [%4];"
                 : "=r"(r0), "=r"(r1), "=r"(r2), "=r"(r3) : "r"(addr));
}

__device__ __forceinline__ void mma_bf16(float* d, const u32* a, u32 b0, u32 b1) {
    asm volatile(
        "mma.sync.aligned.m16n8k16.row.col.f32.bf16.bf16.f32 "
        "{%0,%1,%2,%3}, {%4,%5,%6,%7}, {%8,%9}, {%0,%1,%2,%3};"
        : "+f"(d[0]), "+f"(d[1]), "+f"(d[2]), "+f"(d[3])
        : "r"(a[0]), "r"(a[1]), "r"(a[2]), "r"(a[3]), "r"(b0), "r"(b1));
}

__global__ __launch_bounds__(BLOCK, 5)
void ParallelLinear_59133109732019_kernel(
    const float* __restrict__ x,     // [B, T, 64]
    const float* __restrict__ W,     // [T, 64, 64]  (W[t][o][i])
    const float* __restrict__ bias,  // [T, 64]
    float* __restrict__ out)         // [B, T, 64]
{
    extern __shared__ char smem[];
    const u32 sb = smem_u32(smem);

    const int t       = blockIdx.y;
    const int rowBase = blockIdx.x * ROWS;
    const int tid     = threadIdx.x;
    const int wid     = tid >> 5;
    const int lane    = tid & 31;
    const int g       = lane >> 2;       // row within 8-group
    const int q       = lane & 3;        // fragment column selector

    // x fragment base: rows (rowBase + wid*32 + mt*16 + g [+8]), col 4q (k-permuted)
    const size_t xrstride = (size_t)TT * KK;
    const float* xbase[2];
    #pragma unroll
    for (int mt = 0; mt < 2; mt++)
        xbase[mt] = x + (size_t)(rowBase + wid * 32 + mt * 16 + g) * xrstride
                      + (size_t)t * KK + 4 * q;

    // ---- prefetch ks=0 x data (overlaps the W prologue) ----
    float4 xf[2][2];
    #pragma unroll
    for (int mt = 0; mt < 2; mt++) {
        xf[mt][0] = *(const float4*)(xbase[mt]);                  // row g
        xf[mt][1] = *(const float4*)(xbase[mt] + 8 * xrstride);   // row g+8
    }

    // ---- stage W[t] hi/lo with k-perm (sigma) and n-perm (pi) baked in ----
    {
        const float2* Wg = (const float2*)(W + (size_t)t * (OO * KK));
        #pragma unroll
        for (int k = 0; k < (OO * KK / 2) / BLOCK; k++) {  // 16 iters
            int p = k * BLOCK + tid;
            int o = p >> 5, ip = p & 31;                   // o row, source i-pair
            u32 hi, lo;
            float2 v = Wg[p];
            split2(v.x, v.y, hi, lo);
            // k-perm: pair cp within 16-block -> cp' = (cp&1)*4 + (cp>>1)
            int blk = ip >> 3, cp = ip & 7;
            int ipp = (blk << 3) | (((cp & 1) << 2) | (cp >> 1));
            // n-perm: o = 16m + 4q + 2b + j -> row' = 16m + 8b + 2q + j
            int m = o >> 4, qq = (o >> 2) & 3, bb = (o >> 1) & 1, j = o & 1;
            int rowp = (m << 4) | (bb << 3) | (qq << 1) | j;
            u32 off = stage_off(rowp, ipp);
            *(u32*)(smem + SM_BHI + off) = hi;
            *(u32*)(smem + SM_BLO + off) = lo;
        }
        if (tid < OO) ((float*)(smem + SM_BIAS))[tid] = bias[(size_t)t * OO + tid];
    }
    __syncthreads();

    // ---- accumulators: 2 m-tiles x 8 n-tiles x 4 fp32 ----
    float d[2][8][4];
    #pragma unroll
    for (int mt = 0; mt < 2; mt++)
        #pragma unroll
        for (int nt = 0; nt < 8; nt++)
            #pragma unroll
            for (int e = 0; e < 4; e++) d[mt][nt][e] = 0.0f;

    // B-fragment ldmatrix lane->address components
    const int b_row  = (lane & 7) + ((lane >> 4) << 3);
    const int b_cadd = (lane >> 3) & 1;

    #pragma unroll
    for (int ks = 0; ks < 4; ks++) {
        // x fragments: ks=0 from prologue prefetch, ks>=1 just-in-time
        float4 f00, f01, f10, f11;
        if (ks == 0) {
            f00 = xf[0][0]; f01 = xf[0][1];
            f10 = xf[1][0]; f11 = xf[1][1];
        } else {
            const float* bp0 = xbase[0] + ks * 16;
            const float* bp1 = xbase[1] + ks * 16;
            f00 = *(const float4*)(bp0);
            f01 = *(const float4*)(bp0 + 8 * xrstride);
            f10 = *(const float4*)(bp1);
            f11 = *(const float4*)(bp1 + 8 * xrstride);
        }

        // build bf16 hi/lo A fragments (k-permuted: float4 -> R0/R2, R1/R3)
        u32 ah[2][4], al[2][4];
        split2(f00.x, f00.y, ah[0][0], al[0][0]);
        split2(f01.x, f01.y, ah[0][1], al[0][1]);
        split2(f00.z, f00.w, ah[0][2], al[0][2]);
        split2(f01.z, f01.w, ah[0][3], al[0][3]);
        split2(f10.x, f10.y, ah[1][0], al[1][0]);
        split2(f11.x, f11.y, ah[1][1], al[1][1]);
        split2(f10.z, f10.w, ah[1][2], al[1][2]);
        split2(f11.z, f11.w, ah[1][3], al[1][3]);

        const int c0 = ks * 2;
        #pragma unroll
        for (int np = 0; np < 4; np++) {
            int n  = np * 16 + b_row;
            int ch = c0 + b_cadd;
            u32 off = (u32)(n * 128 + (((ch ^ (n & 7)) & 7) << 4));
            u32 bh0, bh1, bh2, bh3, bl0, bl1, bl2, bl3;
            ldmx4(bh0, bh1, bh2, bh3, sb + SM_BHI + off);
            ldmx4(bl0, bl1, bl2, bl3, sb + SM_BLO + off);

            #pragma unroll
            for (int mt = 0; mt < 2; mt++) {
                mma_bf16(d[mt][2 * np],     ah[mt], bh0, bh1);   // hi*hi
                mma_bf16(d[mt][2 * np + 1], ah[mt], bh2, bh3);
                mma_bf16(d[mt][2 * np],     ah[mt], bl0, bl1);   // hi*lo
                mma_bf16(d[mt][2 * np + 1], ah[mt], bl2, bl3);
                mma_bf16(d[mt][2 * np],     al[mt], bh0, bh1);   // lo*hi
                mma_bf16(d[mt][2 * np + 1], al[mt], bh2, bh3);
            }
        }
    }

    // ---- epilogue: n-perm makes nt-pairs contiguous -> STG.128 ----
    const float* sBias = (const float*)(smem + SM_BIAS);
    #pragma unroll
    for (int mt = 0; mt < 2; mt++) {
        int r0 = rowBase + wid * 32 + mt * 16 + g;
        float* o0 = out + (size_t)r0 * (TT * OO) + (size_t)t * OO;
        float* o1 = o0 + (size_t)8 * (TT * OO);
        #pragma unroll
        for (int m = 0; m < 4; m++) {
            int c = 16 * m + 4 * q;        // true cols c..c+3
            float4 bv = *(const float4*)(sBias + c);
            float4 v0 = { d[mt][2 * m][0] + bv.x, d[mt][2 * m][1] + bv.y,
                          d[mt][2 * m + 1][0] + bv.z, d[mt][2 * m + 1][1] + bv.w };
            float4 v1 = { d[mt][2 * m][2] + bv.x, d[mt][2 * m][3] + bv.y,
                          d[mt][2 * m + 1][2] + bv.z, d[mt][2 * m + 1][3] + bv.w };
            *(float4*)(o0 + c) = v0;       // row r0
            *(float4*)(o1 + c) = v1;       // row r0 + 8
        }
    }
}

extern "C" void kernel_launch(void* const* d_in, const int* in_sizes, int n_in,
                              void* d_out, int out_size)
{
    const float* x    = (const float*)d_in[0];   // 512*1024*64 fp32
    const float* W    = (const float*)d_in[1];   // 1024*64*64 fp32
    const float* bias = (const float*)d_in[2];   // 1024*64 fp32
    float* out        = (float*)d_out;           // 512*1024*64 fp32

    cudaFuncSetAttribute(ParallelLinear_59133109732019_kernel,
                         cudaFuncAttributeMaxDynamicSharedMemorySize, SM_TOTAL);

    dim3 grid(BB / ROWS, TT);   // (4, 1024)
    ParallelLinear_59133109732019_kernel<<<grid, BLOCK, SM_TOTAL>>>(x, W, bias, out);
}